// round 15
// baseline (speedup 1.0000x reference)
#include <cuda_runtime.h>
#include <cstdint>

// ============================================================
// Linear y = x@W + b, x:[262144,128] f32, W:[128,128] f32, b:[128] f32.
// mma.sync m16n8k8 tf32. R15: ONE CTA x 512 thr per SM (16 warps -> 4 per
// SMSP for latency hiding), warp grid 4M x 4N, warp tile 32x32.
// B (W^T tf32) lives in SMEM (64KB), loaded ONCE per persistent CTA;
// B fragments come from ldmatrix (same reg layout as the B-in-regs scheme).
// A tiles 128x128 double-buffered via cp.async. ~90 live regs, no spills.
// ============================================================

#define BATCH    262144
#define NF       128
#define TILE_M   128
#define NTILES   (BATCH / TILE_M)   // 2048
#define GRID     148
#define THREADS  512                // 16 warps: 4 (M) x 4 (N)
#define NBUF     2

#define SM_BUF_BYTES 65536          // one A tile (128 rows x 512B)
#define SM_B_OFF     (NBUF * SM_BUF_BYTES)   // 131072
#define SM_TOTAL     (SM_B_OFF + 65536)      // 196608 (192KB)

// W^T, tf32-rounded, [n][k] row-major
__device__ float g_WT[NF * NF];

__global__ __launch_bounds__(128) void prep_kernel(const float* __restrict__ W) {
    int idx = blockIdx.x * 128 + threadIdx.x;   // 0..16383
    int n = idx >> 7;
    int k = idx & 127;
    float v = W[k * NF + n];
    uint32_t t;
    asm("cvt.rna.tf32.f32 %0, %1;" : "=r"(t) : "f"(v));
    g_WT[n * NF + k] = __uint_as_float(t);
}

__device__ __forceinline__ uint32_t smem_u32(const void* p) {
    uint32_t a;
    asm("{ .reg .u64 t; cvta.to.shared.u64 t, %1; cvt.u32.u64 %0, t; }" : "=r"(a) : "l"(p));
    return a;
}

__device__ __forceinline__ void ldm4(uint32_t& r0, uint32_t& r1, uint32_t& r2, uint32_t& r3,
                                     uint32_t addr) {
    asm volatile("ldmatrix.sync.aligned.m8n8.x4.shared.b16 {%0,%1,%2,%3}, [%4];"
                 : "=r"(r0), "=r"(r1), "=r"(r2), "=r"(r3) : "r"(addr));
}

__device__ __forceinline__ void mma_tf32(float& c0, float& c1, float& c2, float& c3,
                                         uint32_t a0, uint32_t a1, uint32_t a2, uint32_t a3,
                                         uint32_t b0, uint32_t b1) {
    asm volatile(
        "mma.sync.aligned.m16n8k8.row.col.f32.tf32.tf32.f32 "
        "{%0,%1,%2,%3}, {%4,%5,%6,%7}, {%8,%9}, {%0,%1,%2,%3};"
        : "+f"(c0), "+f"(c1), "+f"(c2), "+f"(c3)
        : "r"(a0), "r"(a1), "r"(a2), "r"(a3), "r"(b0), "r"(b1));
}

// Load one 128x128 f32 A tile into smem with per-8-row 16B-chunk XOR swizzle:
// phys(row, chunk) = row*512 + ((chunk ^ (row&7)) << 4), chunk = 0..31.
__device__ __forceinline__ void load_tile(uint32_t sdst, const float* __restrict__ gx, int tid) {
    #pragma unroll
    for (int i = 0; i < 8; i++) {
        int id  = tid + i * THREADS;          // 0..4095
        int row = id >> 5;                    // 0..127
        int c   = id & 31;
        uint32_t dst = sdst + row * 512 + ((c ^ (row & 7)) << 4);
        const float* src = gx + row * NF + c * 4;
        asm volatile("cp.async.cg.shared.global [%0], [%1], 16;" :: "r"(dst), "l"(src) : "memory");
    }
}

__global__ __launch_bounds__(THREADS, 1) void gemm_kernel(const float* __restrict__ x,
                                                          const float* __restrict__ bias,
                                                          float* __restrict__ out) {
    extern __shared__ char smem[];
    const uint32_t sbase = smem_u32(smem);
    const int tid  = threadIdx.x;
    const int lane = tid & 31;
    const int wid  = tid >> 5;      // 0..15
    const int mr   = wid >> 2;      // M warp row (0..3), 32 rows each
    const int ncw  = wid & 3;       // N warp col (0..3), 32 cols each
    const int g    = lane >> 2;     // groupID
    const int tig  = lane & 3;      // threadID_in_group

    // ---- copy B image (W^T tf32) into smem once, swizzled like A ----
    {
        const float4* src = reinterpret_cast<const float4*>(g_WT);
        #pragma unroll
        for (int i = 0; i < 8; i++) {
            int id = tid + i * THREADS;       // 0..4095 chunks
            int n  = id >> 5;
            int c  = id & 31;
            uint32_t dst = sbase + SM_B_OFF + n * 512 + ((c ^ (n & 7)) << 4);
            float4 v = src[id];
            asm volatile("st.shared.v4.b32 [%0], {%1,%2,%3,%4};"
                         :: "r"(dst), "r"(__float_as_uint(v.x)), "r"(__float_as_uint(v.y)),
                            "r"(__float_as_uint(v.z)), "r"(__float_as_uint(v.w)) : "memory");
        }
    }

    // bias registers: cols ncw*32 + nt*8 + 2*tig (+1)
    float bs0[4], bs1[4];
    #pragma unroll
    for (int nt = 0; nt < 4; nt++) {
        int col = ncw * 32 + nt * 8 + 2 * tig;
        bs0[nt] = bias[col];
        bs1[nt] = bias[col + 1];
    }

    // per-lane address components
    const int row16    = lane & 15;      // A: row within m16 tile
    const int chunk_hi = lane >> 4;      // A: 0/1 -> k cols 0-3 / 4-7
    const int a_swz    = (row16 & 7) << 4;
    // B ldm4 lane mapping: lanes 0-7 -> n 0-7 klo | 8-15 -> n 0-7 khi |
    //                      16-23 -> n 8-15 klo   | 24-31 -> n 8-15 khi
    const int n_part     = (lane & 7) + ((lane & 16) >> 1);   // 0..15
    const int lane_chunk = (lane >> 3) & 1;
    const int b_swz      = (lane & 7) << 4;
    const uint32_t b_row_base = sbase + SM_B_OFF + (ncw * 32 + n_part) * 512;

    const int t0 = blockIdx.x;

    // prologue: prefetch tile t0 into buf0
    load_tile(sbase, x + (size_t)t0 * TILE_M * NF, tid);
    asm volatile("cp.async.commit_group;" ::: "memory");

    int bi = 0;

    for (int t = t0; t < NTILES; t += GRID) {
        // prefetch next tile into the other buffer
        int tn = t + GRID;
        if (tn < NTILES)
            load_tile(sbase + (bi ^ 1) * SM_BUF_BYTES, x + (size_t)tn * TILE_M * NF, tid);
        asm volatile("cp.async.commit_group;" ::: "memory");
        asm volatile("cp.async.wait_group 1;" ::: "memory");   // tile t resident
        __syncthreads();   // also orders the one-time B copy before first use

        // ---- compute: warp tile 32(M) x 32(N), K=128 ----
        float acc[2][4][4];
        #pragma unroll
        for (int mt = 0; mt < 2; mt++)
            #pragma unroll
            for (int nt = 0; nt < 4; nt++) {
                acc[mt][nt][0] = 0.f; acc[mt][nt][1] = 0.f;
                acc[mt][nt][2] = 0.f; acc[mt][nt][3] = 0.f;
            }

        const uint32_t abuf = sbase + bi * SM_BUF_BYTES + (mr * 32 + row16) * 512;

        #pragma unroll
        for (int ks = 0; ks < 16; ks++) {
            // A fragments for mt = 0,1 (16 rows each)
            uint32_t a0[4], a1[4];
            {
                uint32_t ka = (((2 * ks + chunk_hi) << 4) ^ a_swz);
                ldm4(a0[0], a0[1], a0[2], a0[3], abuf + ka);
                ldm4(a1[0], a1[1], a1[2], a1[3], abuf + 16 * 512 + ka);
            }
            // B fragments for nt 0-1 (p=0) and nt 2-3 (p=1)
            uint32_t bA[4], bB[4];
            {
                uint32_t kb = (((2 * ks + lane_chunk) << 4) ^ b_swz);
                ldm4(bA[0], bA[1], bA[2], bA[3], b_row_base + kb);
                ldm4(bB[0], bB[1], bB[2], bB[3], b_row_base + 16 * 512 + kb);
            }
            // 8 MMAs
            mma_tf32(acc[0][0][0], acc[0][0][1], acc[0][0][2], acc[0][0][3],
                     a0[0], a0[1], a0[2], a0[3], bA[0], bA[1]);
            mma_tf32(acc[0][1][0], acc[0][1][1], acc[0][1][2], acc[0][1][3],
                     a0[0], a0[1], a0[2], a0[3], bA[2], bA[3]);
            mma_tf32(acc[0][2][0], acc[0][2][1], acc[0][2][2], acc[0][2][3],
                     a0[0], a0[1], a0[2], a0[3], bB[0], bB[1]);
            mma_tf32(acc[0][3][0], acc[0][3][1], acc[0][3][2], acc[0][3][3],
                     a0[0], a0[1], a0[2], a0[3], bB[2], bB[3]);
            mma_tf32(acc[1][0][0], acc[1][0][1], acc[1][0][2], acc[1][0][3],
                     a1[0], a1[1], a1[2], a1[3], bA[0], bA[1]);
            mma_tf32(acc[1][1][0], acc[1][1][1], acc[1][1][2], acc[1][1][3],
                     a1[0], a1[1], a1[2], a1[3], bA[2], bA[3]);
            mma_tf32(acc[1][2][0], acc[1][2][1], acc[1][2][2], acc[1][2][3],
                     a1[0], a1[1], a1[2], a1[3], bB[0], bB[1]);
            mma_tf32(acc[1][3][0], acc[1][3][1], acc[1][3][2], acc[1][3][3],
                     a1[0], a1[1], a1[2], a1[3], bB[2], bB[3]);
        }

        // ---- epilogue: bias add + st.global.v2 ----
        {
            const size_t rbase = (size_t)t * TILE_M + mr * 32;
            #pragma unroll
            for (int mt = 0; mt < 2; mt++) {
                float* r0p = out + (rbase + mt * 16 + g) * NF;
                float* r1p = out + (rbase + mt * 16 + g + 8) * NF;
                #pragma unroll
                for (int nt = 0; nt < 4; nt++) {
                    int col = ncw * 32 + nt * 8 + 2 * tig;
                    float2 v0, v1;
                    v0.x = acc[mt][nt][0] + bs0[nt];
                    v0.y = acc[mt][nt][1] + bs1[nt];
                    v1.x = acc[mt][nt][2] + bs0[nt];
                    v1.y = acc[mt][nt][3] + bs1[nt];
                    *reinterpret_cast<float2*>(r0p + col) = v0;
                    *reinterpret_cast<float2*>(r1p + col) = v1;
                }
            }
        }
        __syncthreads();   // all warps done with buffer bi before it is re-filled
        bi ^= 1;
    }
}

extern "C" void kernel_launch(void* const* d_in, const int* in_sizes, int n_in,
                              void* d_out, int out_size) {
    const float* x    = (const float*)d_in[0];
    const float* W    = (const float*)d_in[1];
    const float* bias = (const float*)d_in[2];
    float* out        = (float*)d_out;

    prep_kernel<<<128, 128>>>(W);

    cudaFuncSetAttribute(gemm_kernel, cudaFuncAttributeMaxDynamicSharedMemorySize, SM_TOTAL);
    gemm_kernel<<<GRID, THREADS, SM_TOTAL>>>(x, bias, out);
}

// round 16
// speedup vs baseline: 1.0964x; 1.0964x over previous
#include <cuda_runtime.h>
#include <cstdint>

// ============================================================
// Linear y = x@W + b, x:[262144,128] f32, W:[128,128] f32, b:[128] f32.
// mma.sync m16n8k8 tf32, 2 CTAs x 128 thr, warp tile 64x32, B (W^T tf32)
// fully in registers, 3-stage cp.async pipeline  (= R5, best known config).
// R16 = R5 + ONE change: prep_kernel deleted; B fragments are loaded
// directly from global W with in-kernel cvt.rna.tf32 in the one-time
// prologue (W is L2-resident). Removes the ~3.5-4us second-launch overhead
// seen every round between harness dur_us and the ncu kernel time.
// ============================================================

#define BATCH    262144
#define NF       128
#define TILE_M   64
#define NTILES   (BATCH / TILE_M)   // 4096
#define GRID     296                // 2 CTAs x 148 SMs
#define THREADS  128                // 4 warps: 1 (M) x 4 (N)
#define NBUF     3

#define SM_BUF_BYTES 32768          // one A tile (64 rows x 512B)
#define SM_TOTAL     (NBUF * SM_BUF_BYTES)

__device__ __forceinline__ uint32_t smem_u32(const void* p) {
    uint32_t a;
    asm("{ .reg .u64 t; cvta.to.shared.u64 t, %1; cvt.u32.u64 %0, t; }" : "=r"(a) : "l"(p));
    return a;
}

__device__ __forceinline__ float tf32_rna(float v) {
    uint32_t t;
    asm("cvt.rna.tf32.f32 %0, %1;" : "=r"(t) : "f"(v));
    return __uint_as_float(t);
}

__device__ __forceinline__ void ldm4(uint32_t& r0, uint32_t& r1, uint32_t& r2, uint32_t& r3,
                                     uint32_t addr) {
    asm volatile("ldmatrix.sync.aligned.m8n8.x4.shared.b16 {%0,%1,%2,%3}, [%4];"
                 : "=r"(r0), "=r"(r1), "=r"(r2), "=r"(r3) : "r"(addr));
}

__device__ __forceinline__ void mma_tf32(float& c0, float& c1, float& c2, float& c3,
                                         uint32_t a0, uint32_t a1, uint32_t a2, uint32_t a3,
                                         float bf0, float bf1) {
    uint32_t b0 = __float_as_uint(bf0), b1 = __float_as_uint(bf1);
    asm volatile(
        "mma.sync.aligned.m16n8k8.row.col.f32.tf32.tf32.f32 "
        "{%0,%1,%2,%3}, {%4,%5,%6,%7}, {%8,%9}, {%0,%1,%2,%3};"
        : "+f"(c0), "+f"(c1), "+f"(c2), "+f"(c3)
        : "r"(a0), "r"(a1), "r"(a2), "r"(a3), "r"(b0), "r"(b1));
}

// Load one 64x128 f32 A tile into smem with per-8-row 16B-chunk XOR swizzle:
// phys(row, chunk) = row*512 + ((chunk ^ (row&7)) << 4), chunk = 0..31.
__device__ __forceinline__ void load_tile(uint32_t sdst, const float* __restrict__ gx, int tid) {
    #pragma unroll
    for (int i = 0; i < 16; i++) {
        int id  = tid + i * THREADS;          // 0..2047
        int row = id >> 5;                    // 0..63
        int c   = id & 31;
        uint32_t dst = sdst + row * 512 + ((c ^ (row & 7)) << 4);
        const float* src = gx + row * NF + c * 4;
        asm volatile("cp.async.cg.shared.global [%0], [%1], 16;" :: "r"(dst), "l"(src) : "memory");
    }
}

__global__ __launch_bounds__(THREADS, 2) void gemm_kernel(const float* __restrict__ x,
                                                          const float* __restrict__ W,
                                                          const float* __restrict__ bias,
                                                          float* __restrict__ out) {
    extern __shared__ char smem[];
    const uint32_t sbase = smem_u32(smem);
    const int tid  = threadIdx.x;
    const int lane = tid & 31;
    const int nc   = tid >> 5;      // warp id = N column (0..3)
    const int g    = lane >> 2;     // groupID (row within 8)
    const int tig  = lane & 3;      // threadID_in_group

    const int t0 = blockIdx.x;

    // prologue: prefetch 2 tiles first so the one-time B load overlaps the
    // initial DRAM latency (t0, t0+GRID always < NTILES since t0 < 296)
    load_tile(sbase + 0 * SM_BUF_BYTES, x + (size_t)t0 * TILE_M * NF, tid);
    asm volatile("cp.async.commit_group;" ::: "memory");
    load_tile(sbase + 1 * SM_BUF_BYTES, x + (size_t)(t0 + GRID) * TILE_M * NF, tid);
    asm volatile("cp.async.commit_group;" ::: "memory");

    // ---- B fragments in registers, read directly from global W (one-time).
    // b0[nt][ks] = tf32(W[k][n]) with k = ks*8+tig, n = nc*32+nt*8+g;
    // b1 uses k+4. W is 64KB -> L2-resident; cost amortized over ~14 tiles.
    float b0[4][16], b1[4][16];
    #pragma unroll
    for (int nt = 0; nt < 4; nt++) {
        int n = nc * 32 + nt * 8 + g;
        #pragma unroll
        for (int ks = 0; ks < 16; ks++) {
            b0[nt][ks] = tf32_rna(W[(ks * 8 + tig) * NF + n]);
            b1[nt][ks] = tf32_rna(W[(ks * 8 + tig + 4) * NF + n]);
        }
    }
    float bs0[4], bs1[4];
    #pragma unroll
    for (int nt = 0; nt < 4; nt++) {
        int col = nc * 32 + nt * 8 + 2 * tig;
        bs0[nt] = bias[col];
        bs1[nt] = bias[col + 1];
    }

    const int arow_in16 = lane & 15;     // row within m16 tile
    const int chunk_hi  = lane >> 4;     // 0/1: cols 0-3 vs 4-7

    int bi = 0;   // buffer holding tile t

    for (int t = t0; t < NTILES; t += GRID) {
        // prefetch tile t+2*GRID into buffer (bi+2)%3
        int tn = t + 2 * GRID;
        if (tn < NTILES) {
            int bn = bi + 2; if (bn >= NBUF) bn -= NBUF;
            load_tile(sbase + bn * SM_BUF_BYTES, x + (size_t)tn * TILE_M * NF, tid);
        }
        asm volatile("cp.async.commit_group;" ::: "memory");
        asm volatile("cp.async.wait_group 2;" ::: "memory");   // tile t resident
        __syncthreads();

        // ---- compute: warp tile 64(M) x 32(N), K=128 ----
        float acc[4][4][4];
        #pragma unroll
        for (int mt = 0; mt < 4; mt++)
            #pragma unroll
            for (int nt = 0; nt < 4; nt++) {
                acc[mt][nt][0] = 0.f; acc[mt][nt][1] = 0.f;
                acc[mt][nt][2] = 0.f; acc[mt][nt][3] = 0.f;
            }

        const uint32_t sbuf = sbase + bi * SM_BUF_BYTES;
        #pragma unroll
        for (int ks = 0; ks < 16; ks++) {
            uint32_t a[4][4];
            #pragma unroll
            for (int mt = 0; mt < 4; mt++) {
                int row   = mt * 16 + arow_in16;
                int chunk = 2 * ks + chunk_hi;
                uint32_t addr = sbuf + row * 512 + ((chunk ^ (row & 7)) << 4);
                ldm4(a[mt][0], a[mt][1], a[mt][2], a[mt][3], addr);
            }
            #pragma unroll
            for (int mt = 0; mt < 4; mt++)
                #pragma unroll
                for (int nt = 0; nt < 4; nt++)
                    mma_tf32(acc[mt][nt][0], acc[mt][nt][1], acc[mt][nt][2], acc[mt][nt][3],
                             a[mt][0], a[mt][1], a[mt][2], a[mt][3],
                             b0[nt][ks], b1[nt][ks]);
        }

        // ---- epilogue: bias add + st.global.v2 ----
        {
            const size_t rbase = (size_t)t * TILE_M;
            #pragma unroll
            for (int mt = 0; mt < 4; mt++) {
                int r = mt * 16 + g;
                #pragma unroll
                for (int nt = 0; nt < 4; nt++) {
                    int col = nc * 32 + nt * 8 + 2 * tig;
                    float2 v0, v1;
                    v0.x = acc[mt][nt][0] + bs0[nt];
                    v0.y = acc[mt][nt][1] + bs1[nt];
                    v1.x = acc[mt][nt][2] + bs0[nt];
                    v1.y = acc[mt][nt][3] + bs1[nt];
                    *reinterpret_cast<float2*>(out + (rbase + r) * NF + col)     = v0;
                    *reinterpret_cast<float2*>(out + (rbase + r + 8) * NF + col) = v1;
                }
            }
        }
        __syncthreads();   // all warps done with buffer bi before it is re-filled
        bi = bi + 1; if (bi >= NBUF) bi -= NBUF;
    }
}

extern "C" void kernel_launch(void* const* d_in, const int* in_sizes, int n_in,
                              void* d_out, int out_size) {
    const float* x    = (const float*)d_in[0];
    const float* W    = (const float*)d_in[1];
    const float* bias = (const float*)d_in[2];
    float* out        = (float*)d_out;

    cudaFuncSetAttribute(gemm_kernel, cudaFuncAttributeMaxDynamicSharedMemorySize, SM_TOTAL);
    gemm_kernel<<<GRID, THREADS, SM_TOTAL>>>(x, W, bias, out);
}